// round 1
// baseline (speedup 1.0000x reference)
#include <cuda_runtime.h>
#include <math.h>
#include <float.h>

#define D      128
#define PAD    132          // 128 + 4 pad: conflict-free LDS.128 / STS.128
#define BM     32
#define BN     128
#define TOPK   5
#define THREADS 256

__device__ float g_a2[8192];
__device__ float g_b2[16384];
__device__ float g_partials[1024];

// ---------------------------------------------------------------------------
// Row squared norms: one warp per row (32 lanes x float4 = 128 floats)
// ---------------------------------------------------------------------------
__global__ void norms_kernel(const float* __restrict__ pred,
                             const float* __restrict__ tgt,
                             int N, int M) {
    int row  = blockIdx.x * 8 + (threadIdx.x >> 5);
    int lane = threadIdx.x & 31;
    if (row >= N + M) return;
    const float* src = (row < M) ? (tgt + (size_t)row * D)
                                 : (pred + (size_t)(row - M) * D);
    float4 v = ((const float4*)src)[lane];
    float s = v.x * v.x + v.y * v.y + v.z * v.z + v.w * v.w;
    #pragma unroll
    for (int off = 16; off; off >>= 1)
        s += __shfl_xor_sync(0xffffffffu, s, off);
    if (lane == 0) {
        if (row < M) g_b2[row] = s;
        else         g_a2[row - M] = s;
    }
}

// ---------------------------------------------------------------------------
// Main: fused distance GEMM + per-row top-5 (on key = ||b||^2 - 2 a.b)
// Block: 32 pred rows x all M targets (tiled by 128). 8 warps; warp w owns
// pred rows 4w..4w+3; lane owns targets lane+32i, i=0..3, per tile.
// ---------------------------------------------------------------------------
extern __shared__ float smem[];

__global__ __launch_bounds__(THREADS, 2)
void density_main(const float* __restrict__ pred,
                  const float* __restrict__ tgt,
                  int N, int M) {
    float* sa    = smem;                    // [BM][PAD]
    float* sb    = sa + BM * PAD;           // [BN][PAD]
    float* sb2   = sb + BN * PAD;           // [BN]
    float* swsum = sb2 + BN;                // [8]

    const int tid  = threadIdx.x;
    const int warp = tid >> 5;
    const int lane = tid & 31;
    const int row0 = blockIdx.x * BM;

    // Load pred tile (coalesced, conflict-free STS.128)
    #pragma unroll
    for (int i = 0; i < 4; i++) {
        int f = tid + i * THREADS;          // float4 index, 1024 total
        int r = f >> 5;                     // 32 float4 per row
        int c = (f & 31) << 2;
        float4 v = *(const float4*)(pred + (size_t)(row0 + r) * D + c);
        *(float4*)(sa + r * PAD + c) = v;
    }

    // Per-thread sorted (ascending) top-5 keys for each of 4 owned rows
    float t5[4][TOPK];
    #pragma unroll
    for (int r = 0; r < 4; r++)
        #pragma unroll
        for (int s = 0; s < TOPK; s++)
            t5[r][s] = FLT_MAX;

    for (int t0 = 0; t0 < M; t0 += BN) {
        __syncthreads();                    // protect sb before overwrite
        #pragma unroll
        for (int i = 0; i < 16; i++) {
            int f = tid + i * THREADS;      // 4096 float4
            int r = f >> 5;
            int c = (f & 31) << 2;
            float4 v = *(const float4*)(tgt + (size_t)(t0 + r) * D + c);
            *(float4*)(sb + r * PAD + c) = v;
        }
        if (tid < BN) sb2[tid] = g_b2[t0 + tid];
        __syncthreads();

        float acc[4][4];
        #pragma unroll
        for (int r = 0; r < 4; r++)
            #pragma unroll
            for (int i = 0; i < 4; i++)
                acc[r][i] = 0.0f;

        #pragma unroll 4
        for (int k0 = 0; k0 < D; k0 += 4) {
            float4 av[4], bv[4];
            #pragma unroll
            for (int r = 0; r < 4; r++)
                av[r] = *(const float4*)(sa + (4 * warp + r) * PAD + k0);
            #pragma unroll
            for (int i = 0; i < 4; i++)
                bv[i] = *(const float4*)(sb + (lane + 32 * i) * PAD + k0);
            #pragma unroll
            for (int r = 0; r < 4; r++)
                #pragma unroll
                for (int i = 0; i < 4; i++) {
                    acc[r][i] = fmaf(av[r].x, bv[i].x, acc[r][i]);
                    acc[r][i] = fmaf(av[r].y, bv[i].y, acc[r][i]);
                    acc[r][i] = fmaf(av[r].z, bv[i].z, acc[r][i]);
                    acc[r][i] = fmaf(av[r].w, bv[i].w, acc[r][i]);
                }
        }

        // keys + top-5 insert (branch is rarely taken after warmup)
        #pragma unroll
        for (int i = 0; i < 4; i++) {
            float b2v = sb2[lane + 32 * i];
            #pragma unroll
            for (int r = 0; r < 4; r++) {
                float key = fmaf(-2.0f, acc[r][i], b2v);
                if (key < t5[r][TOPK - 1]) {
                    t5[r][TOPK - 1] = key;
                    #pragma unroll
                    for (int s = TOPK - 1; s > 0; --s) {
                        float lo = fminf(t5[r][s - 1], t5[r][s]);
                        float hi = fmaxf(t5[r][s - 1], t5[r][s]);
                        t5[r][s - 1] = lo;
                        t5[r][s]     = hi;
                    }
                }
            }
        }
    }

    // Warp-level merge: global top-5 per row from 32 lanes' sorted lists.
    // Each lane's candidate is its current front t5[r][0]; pop = static shift.
    float wsum = 0.0f;
    #pragma unroll
    for (int r = 0; r < 4; r++) {
        float a2r = g_a2[row0 + 4 * warp + r];
        #pragma unroll
        for (int s = 0; s < TOPK; s++) {
            float myv = t5[r][0];
            float m = myv;
            #pragma unroll
            for (int off = 16; off; off >>= 1)
                m = fminf(m, __shfl_xor_sync(0xffffffffu, m, off));
            unsigned bal = __ballot_sync(0xffffffffu, myv == m);
            int leader = __ffs((int)bal) - 1;
            if (lane == leader) {
                t5[r][0] = t5[r][1];
                t5[r][1] = t5[r][2];
                t5[r][2] = t5[r][3];
                t5[r][3] = t5[r][4];
                t5[r][4] = FLT_MAX;
            }
            float d2 = fmaxf(a2r + m, 0.0f);
            wsum += fmaxf(sqrtf(d2) - 1.0f, 0.0f);
        }
    }

    __syncthreads();
    if (lane == 0) swsum[warp] = wsum;
    __syncthreads();
    if (tid == 0) {
        float s = 0.0f;
        #pragma unroll
        for (int w = 0; w < 8; w++) s += swsum[w];
        g_partials[blockIdx.x] = s;
    }
}

// ---------------------------------------------------------------------------
// Final deterministic reduce of per-block partials
// ---------------------------------------------------------------------------
__global__ void reduce_kernel(float* __restrict__ out, int nblocks, float scale) {
    __shared__ float ws[8];
    float s = 0.0f;
    for (int i = threadIdx.x; i < nblocks; i += 256)
        s += g_partials[i];
    #pragma unroll
    for (int off = 16; off; off >>= 1)
        s += __shfl_xor_sync(0xffffffffu, s, off);
    if ((threadIdx.x & 31) == 0) ws[threadIdx.x >> 5] = s;
    __syncthreads();
    if (threadIdx.x == 0) {
        float t = 0.0f;
        #pragma unroll
        for (int w = 0; w < 8; w++) t += ws[w];
        out[0] = t * scale;
    }
}

extern "C" void kernel_launch(void* const* d_in, const int* in_sizes, int n_in,
                              void* d_out, int out_size) {
    const float* pred = (const float*)d_in[0];
    const float* tgt  = (const float*)d_in[1];
    int N = in_sizes[0] / D;    // 8192
    int M = in_sizes[1] / D;    // 16384

    int nrows = N + M;
    norms_kernel<<<(nrows + 7) / 8, 256>>>(pred, tgt, N, M);

    int nblocks = N / BM;       // 256
    size_t smem_bytes = (size_t)(BM * PAD + BN * PAD + BN + 8) * sizeof(float);
    cudaFuncSetAttribute(density_main,
                         cudaFuncAttributeMaxDynamicSharedMemorySize,
                         (int)smem_bytes);
    density_main<<<nblocks, THREADS, smem_bytes>>>(pred, tgt, N, M);

    reduce_kernel<<<1, 256>>>((float*)d_out, nblocks,
                              1.0f / ((float)N * (float)TOPK));
}

// round 3
// speedup vs baseline: 6.4578x; 6.4578x over previous
#include <cuda_runtime.h>
#include <cuda_fp16.h>
#include <math.h>
#include <float.h>
#include <stdint.h>

#define N_PRED 8192
#define M_TGT  16384
#define KD     128
#define MT     128         // CTA tile M (pred rows)
#define NT     128         // CTA tile N (target rows)
#define CHUNKS 2
#define CHUNK  (M_TGT / CHUNKS)   // 8192
#define TILES  (CHUNK / NT)       // 64
#define TOPK   5
#define ROWB   272         // bytes per padded smem row (136 halves)

// ---------------- static device scratch ----------------
__device__ __half g_pred_h[N_PRED * KD];
__device__ __half g_tgt_h[M_TGT * KD];
__device__ float  g_a2[N_PRED];
__device__ float  g_b2[M_TGT];
// per (chunk, row, warpN) top-5 candidates: [2][8192][4][5]
__device__ float  g_cand[CHUNKS * N_PRED * 4 * TOPK];
__device__ float  g_partials[32];

// ---------------- smem layout (bytes) ----------------
#define SA    0
#define SB0   34816
#define SB1   69632
#define B2_0  104448
#define B2_1  104960
#define SMEM_TOTAL 105472

__device__ __forceinline__ uint32_t smem_u32(const void* p) {
    uint32_t a;
    asm("{ .reg .u64 t; cvta.to.shared.u64 t, %1; cvt.u32.u64 %0, t; }"
        : "=r"(a) : "l"(p));
    return a;
}
__device__ __forceinline__ void cp16(uint32_t dst, const void* src) {
    asm volatile("cp.async.cg.shared.global [%0], [%1], 16;"
                 :: "r"(dst), "l"(src) : "memory");
}
__device__ __forceinline__ void cp4(uint32_t dst, const void* src) {
    asm volatile("cp.async.ca.shared.global [%0], [%1], 4;"
                 :: "r"(dst), "l"(src) : "memory");
}
#define CP_COMMIT() asm volatile("cp.async.commit_group;" ::: "memory")
#define CP_WAIT0()  asm volatile("cp.async.wait_group 0;" ::: "memory")

__device__ __forceinline__ void ldsm4(uint32_t a, uint32_t& r0, uint32_t& r1,
                                      uint32_t& r2, uint32_t& r3) {
    asm volatile("ldmatrix.sync.aligned.m8n8.x4.shared.b16 {%0,%1,%2,%3}, [%4];"
                 : "=r"(r0), "=r"(r1), "=r"(r2), "=r"(r3) : "r"(a));
}
__device__ __forceinline__ void mma16816(float& c0, float& c1, float& c2, float& c3,
                                         uint32_t a0, uint32_t a1, uint32_t a2,
                                         uint32_t a3, uint32_t b0, uint32_t b1) {
    asm volatile("mma.sync.aligned.m16n8k16.row.col.f32.f16.f16.f32 "
                 "{%0,%1,%2,%3}, {%4,%5,%6,%7}, {%8,%9}, {%0,%1,%2,%3};"
                 : "+f"(c0), "+f"(c1), "+f"(c2), "+f"(c3)
                 : "r"(a0), "r"(a1), "r"(a2), "r"(a3), "r"(b0), "r"(b1));
}

#define CE(x, y) { float _lo = fminf(x, y); float _hi = fmaxf(x, y); x = _lo; y = _hi; }

// ---------------- prep: fp32 -> fp16 convert + squared norms ----------------
__global__ void prep_kernel(const float* __restrict__ pred,
                            const float* __restrict__ tgt) {
    int row  = blockIdx.x * 8 + (threadIdx.x >> 5);
    int lane = threadIdx.x & 31;
    if (row >= N_PRED + M_TGT) return;
    const float* src = (row < M_TGT) ? (tgt + (size_t)row * KD)
                                     : (pred + (size_t)(row - M_TGT) * KD);
    float4 v = ((const float4*)src)[lane];
    float s = v.x * v.x + v.y * v.y + v.z * v.z + v.w * v.w;
    #pragma unroll
    for (int off = 16; off; off >>= 1)
        s += __shfl_xor_sync(0xffffffffu, s, off);
    __half2 h0 = __floats2half2_rn(v.x, v.y);
    __half2 h1 = __floats2half2_rn(v.z, v.w);
    uint2 u;
    u.x = *reinterpret_cast<unsigned*>(&h0);
    u.y = *reinterpret_cast<unsigned*>(&h1);
    __half* dst = (row < M_TGT) ? (g_tgt_h + (size_t)row * KD)
                                : (g_pred_h + (size_t)(row - M_TGT) * KD);
    *(uint2*)(dst + lane * 4) = u;
    if (lane == 0) {
        if (row < M_TGT) g_b2[row] = s;
        else             g_a2[row - M_TGT] = s;
    }
}

// ---------------- main: HMMA GEMM + fused per-row top-5 ----------------
extern __shared__ char smem[];

__global__ __launch_bounds__(256, 1) void mma_main() {
    const int tid   = threadIdx.x;
    const int wid   = tid >> 5;
    const int lane  = tid & 31;
    const int warpM = wid >> 2;      // 0..1
    const int warpN = wid & 3;       // 0..3
    const uint32_t sbase = smem_u32(smem);

    const int row0 = blockIdx.x * MT;
    const int tb0  = blockIdx.y * CHUNK;

    // ---- prologue: A tile + B tile 0 + b2 0 via cp.async ----
    {
        const char* gA = (const char*)g_pred_h + (size_t)row0 * 256;
        const char* gB = (const char*)g_tgt_h + (size_t)tb0 * 256;
        #pragma unroll
        for (int i = 0; i < 8; i++) {
            int cix = tid + i * 256;         // 2048 chunks of 16B
            int r = cix >> 4, c = cix & 15;
            cp16(sbase + SA + r * ROWB + c * 16, gA + (size_t)r * 256 + c * 16);
            cp16(sbase + SB0 + r * ROWB + c * 16, gB + (size_t)r * 256 + c * 16);
        }
        if (tid < 128) cp4(sbase + B2_0 + tid * 4, g_b2 + tb0 + tid);
        CP_COMMIT();
        CP_WAIT0();
    }
    __syncthreads();

    // per-lane ldmatrix base offsets (byte offsets within a tile)
    const uint32_t rowA_off =
        (uint32_t)(warpM * 64 + ((lane >> 3) & 1) * 8 + (lane & 7)) * ROWB +
        (uint32_t)(lane >> 4) * 16;
    const uint32_t rowB_off =
        (uint32_t)(warpN * 32 + ((lane >> 4) & 1) * 8 + (lane & 7)) * ROWB +
        (uint32_t)((lane >> 3) & 1) * 16;

    float t5[8][TOPK];
    #pragma unroll
    for (int r = 0; r < 8; r++)
        #pragma unroll
        for (int s = 0; s < TOPK; s++) t5[r][s] = FLT_MAX;

    for (int tile = 0; tile < TILES; tile++) {
        const int p = tile & 1;
        const uint32_t sb_cur = sbase + (p ? SB1 : SB0);
        const uint32_t b2_cur = sbase + (p ? B2_1 : B2_0);

        // prefetch next B tile into the other buffer
        if (tile + 1 < TILES) {
            const uint32_t sb_nxt = sbase + (p ? SB0 : SB1);
            const uint32_t b2_nxt = sbase + (p ? B2_0 : B2_1);
            const int tb = tb0 + (tile + 1) * NT;
            const char* gB = (const char*)g_tgt_h + (size_t)tb * 256;
            #pragma unroll
            for (int i = 0; i < 8; i++) {
                int cix = tid + i * 256;
                int r = cix >> 4, c = cix & 15;
                cp16(sb_nxt + r * ROWB + c * 16, gB + (size_t)r * 256 + c * 16);
            }
            if (tid < 128) cp4(b2_nxt + tid * 4, g_b2 + tb + tid);
            CP_COMMIT();
        }

        // ---- compute C = A . B^T for this 128x128 tile ----
        float acc[4][4][4];
        #pragma unroll
        for (int mf = 0; mf < 4; mf++)
            #pragma unroll
            for (int nf = 0; nf < 4; nf++)
                #pragma unroll
                for (int i = 0; i < 4; i++) acc[mf][nf][i] = 0.0f;

        #pragma unroll
        for (int ks = 0; ks < 8; ks++) {
            uint32_t a[4][4], b[8];
            #pragma unroll
            for (int mf = 0; mf < 4; mf++)
                ldsm4(sbase + SA + rowA_off + mf * (16 * ROWB) + ks * 32,
                      a[mf][0], a[mf][1], a[mf][2], a[mf][3]);
            #pragma unroll
            for (int j = 0; j < 2; j++)
                ldsm4(sb_cur + rowB_off + j * (16 * ROWB) + ks * 32,
                      b[j * 4 + 0], b[j * 4 + 1], b[j * 4 + 2], b[j * 4 + 3]);
            #pragma unroll
            for (int mf = 0; mf < 4; mf++)
                #pragma unroll
                for (int nf = 0; nf < 4; nf++)
                    mma16816(acc[mf][nf][0], acc[mf][nf][1],
                             acc[mf][nf][2], acc[mf][nf][3],
                             a[mf][0], a[mf][1], a[mf][2], a[mf][3],
                             b[nf * 2 + 0], b[nf * 2 + 1]);
        }

        // ---- epilogue: keys + top-5 insert ----
        float bb[8];
        #pragma unroll
        for (int nf = 0; nf < 4; nf++)
            #pragma unroll
            for (int par = 0; par < 2; par++)
                bb[nf * 2 + par] = *(const float*)(smem +
                    (b2_cur - sbase) + (warpN * 32 + nf * 8 + 2 * (lane & 3) + par) * 4);

        #pragma unroll
        for (int mf = 0; mf < 4; mf++)
            #pragma unroll
            for (int nf = 0; nf < 4; nf++)
                #pragma unroll
                for (int i = 0; i < 4; i++) {
                    const int ri = mf * 2 + (i >> 1);
                    float key = fmaf(-2.0f, acc[mf][nf][i], bb[nf * 2 + (i & 1)]);
                    if (key < t5[ri][4]) {
                        t5[ri][4] = key;
                        CE(t5[ri][3], t5[ri][4]);
                        CE(t5[ri][2], t5[ri][3]);
                        CE(t5[ri][1], t5[ri][2]);
                        CE(t5[ri][0], t5[ri][1]);
                    }
                }

        CP_WAIT0();
        __syncthreads();
    }

    // ---- quad merge (lanes sharing the same rows: lane>>2 equal) ----
    #pragma unroll
    for (int r = 0; r < 8; r++) {
        #pragma unroll
        for (int off = 1; off <= 2; off <<= 1) {
            float b[TOPK], m[TOPK];
            #pragma unroll
            for (int s = 0; s < TOPK; s++)
                b[s] = __shfl_xor_sync(0xffffffffu, t5[r][s], off);
            #pragma unroll
            for (int s = 0; s < TOPK; s++)
                m[s] = fminf(t5[r][s], b[TOPK - 1 - s]);
            // bubble network sorts 5 ascending
            CE(m[0], m[1]); CE(m[1], m[2]); CE(m[2], m[3]); CE(m[3], m[4]);
            CE(m[0], m[1]); CE(m[1], m[2]); CE(m[2], m[3]);
            CE(m[0], m[1]); CE(m[1], m[2]);
            CE(m[0], m[1]);
            #pragma unroll
            for (int s = 0; s < TOPK; s++) t5[r][s] = m[s];
        }
    }

    if ((lane & 3) == 0) {
        #pragma unroll
        for (int mf = 0; mf < 4; mf++)
            #pragma unroll
            for (int h = 0; h < 2; h++) {
                int row = row0 + warpM * 64 + mf * 16 + (lane >> 2) + 8 * h;
                size_t base = ((size_t)blockIdx.y * N_PRED + row) * 20 + warpN * 5;
                #pragma unroll
                for (int s = 0; s < TOPK; s++)
                    g_cand[base + s] = t5[mf * 2 + h][s];
            }
    }
}

// ---------------- merge candidates -> hinge partial sums ----------------
__global__ void merge_kernel() {
    __shared__ float ws[8];
    int r = blockIdx.x * 256 + threadIdx.x;
    float t5[TOPK];
    #pragma unroll
    for (int s = 0; s < TOPK; s++) t5[s] = FLT_MAX;
    #pragma unroll
    for (int c = 0; c < CHUNKS; c++)
        #pragma unroll
        for (int j = 0; j < 20; j++) {
            float key = g_cand[((size_t)c * N_PRED + r) * 20 + j];
            if (key < t5[4]) {
                t5[4] = key;
                CE(t5[3], t5[4]); CE(t5[2], t5[3]); CE(t5[1], t5[2]); CE(t5[0], t5[1]);
            }
        }
    float a2 = g_a2[r];
    float sum = 0.0f;
    #pragma unroll
    for (int s = 0; s < TOPK; s++) {
        float d2 = fmaxf(a2 + t5[s], 0.0f);
        sum += fmaxf(sqrtf(d2) - 1.0f, 0.0f);
    }
    #pragma unroll
    for (int off = 16; off; off >>= 1)
        sum += __shfl_xor_sync(0xffffffffu, sum, off);
    if ((threadIdx.x & 31) == 0) ws[threadIdx.x >> 5] = sum;
    __syncthreads();
    if (threadIdx.x == 0) {
        float t = 0.0f;
        #pragma unroll
        for (int w = 0; w < 8; w++) t += ws[w];
        g_partials[blockIdx.x] = t;
    }
}

__global__ void final_kernel(float* __restrict__ out) {
    float s = (threadIdx.x < 32) ? g_partials[threadIdx.x] : 0.0f;
    #pragma unroll
    for (int off = 16; off; off >>= 1)
        s += __shfl_xor_sync(0xffffffffu, s, off);
    if (threadIdx.x == 0)
        out[0] = s * (1.0f / ((float)N_PRED * (float)TOPK));
}

extern "C" void kernel_launch(void* const* d_in, const int* in_sizes, int n_in,
                              void* d_out, int out_size) {
    const float* pred = (const float*)d_in[0];
    const float* tgt  = (const float*)d_in[1];

    prep_kernel<<<(N_PRED + M_TGT + 7) / 8, 256>>>(pred, tgt);

    cudaFuncSetAttribute(mma_main, cudaFuncAttributeMaxDynamicSharedMemorySize,
                         SMEM_TOTAL);
    dim3 grid(N_PRED / MT, CHUNKS);
    mma_main<<<grid, 256, SMEM_TOTAL>>>();

    merge_kernel<<<N_PRED / 256, 256>>>();
    final_kernel<<<1, 32>>>((float*)d_out);
}

// round 4
// speedup vs baseline: 6.6487x; 1.0296x over previous
#include <cuda_runtime.h>
#include <cuda_fp16.h>
#include <math.h>
#include <float.h>
#include <stdint.h>

#define N_PRED 8192
#define M_TGT  16384
#define KD     128
#define MT     128         // CTA tile M (pred rows)
#define NT     64          // CTA tile N (target rows)
#define CHUNKS 4
#define CHUNK  (M_TGT / CHUNKS)   // 4096
#define TILES  (CHUNK / NT)       // 64
#define TOPK   5
#define ROWB   272         // bytes per padded smem row (136 halves)

// ---------------- static device scratch ----------------
__device__ __half g_pred_h[N_PRED * KD];
__device__ __half g_tgt_h[M_TGT * KD];
__device__ float  g_a2[N_PRED];
__device__ float  g_b2[M_TGT];
__device__ float  g_cand[CHUNKS * N_PRED * TOPK];   // [chunk][row][5]
__device__ float  g_partials[32];
__device__ int    g_ticket;

// ---------------- smem layout (bytes), per CTA total 70144 ----------------
#define SA    0
#define SB0   34816
#define SB1   52224
#define B2_0  69632
#define B2_1  69888
#define SMEM_TOTAL 70144

__device__ __forceinline__ uint32_t smem_u32(const void* p) {
    uint32_t a;
    asm("{ .reg .u64 t; cvta.to.shared.u64 t, %1; cvt.u32.u64 %0, t; }"
        : "=r"(a) : "l"(p));
    return a;
}
__device__ __forceinline__ void cp16(uint32_t dst, const void* src) {
    asm volatile("cp.async.cg.shared.global [%0], [%1], 16;"
                 :: "r"(dst), "l"(src) : "memory");
}
__device__ __forceinline__ void cp4(uint32_t dst, const void* src) {
    asm volatile("cp.async.ca.shared.global [%0], [%1], 4;"
                 :: "r"(dst), "l"(src) : "memory");
}
#define CP_COMMIT() asm volatile("cp.async.commit_group;" ::: "memory")
#define CP_WAIT0()  asm volatile("cp.async.wait_group 0;" ::: "memory")

__device__ __forceinline__ void ldsm4(uint32_t a, uint32_t& r0, uint32_t& r1,
                                      uint32_t& r2, uint32_t& r3) {
    asm volatile("ldmatrix.sync.aligned.m8n8.x4.shared.b16 {%0,%1,%2,%3}, [%4];"
                 : "=r"(r0), "=r"(r1), "=r"(r2), "=r"(r3) : "r"(a));
}
__device__ __forceinline__ void mma16816(float* c, uint32_t a0, uint32_t a1,
                                         uint32_t a2, uint32_t a3,
                                         uint32_t b0, uint32_t b1) {
    asm volatile("mma.sync.aligned.m16n8k16.row.col.f32.f16.f16.f32 "
                 "{%0,%1,%2,%3}, {%4,%5,%6,%7}, {%8,%9}, {%0,%1,%2,%3};"
                 : "+f"(c[0]), "+f"(c[1]), "+f"(c[2]), "+f"(c[3])
                 : "r"(a0), "r"(a1), "r"(a2), "r"(a3), "r"(b0), "r"(b1));
}

#define CE(x, y) { float _lo = fminf(x, y); float _hi = fmaxf(x, y); x = _lo; y = _hi; }

// ---------------- prep: fp32 -> fp16 convert + squared norms ----------------
__global__ void prep_kernel(const float* __restrict__ pred,
                            const float* __restrict__ tgt) {
    if (blockIdx.x == 0 && threadIdx.x == 0) g_ticket = 0;
    int row  = blockIdx.x * 8 + (threadIdx.x >> 5);
    int lane = threadIdx.x & 31;
    if (row >= N_PRED + M_TGT) return;
    const float* src = (row < M_TGT) ? (tgt + (size_t)row * KD)
                                     : (pred + (size_t)(row - M_TGT) * KD);
    float4 v = ((const float4*)src)[lane];
    float s = v.x * v.x + v.y * v.y + v.z * v.z + v.w * v.w;
    #pragma unroll
    for (int off = 16; off; off >>= 1)
        s += __shfl_xor_sync(0xffffffffu, s, off);
    __half2 h0 = __floats2half2_rn(v.x, v.y);
    __half2 h1 = __floats2half2_rn(v.z, v.w);
    uint2 u;
    u.x = *reinterpret_cast<unsigned*>(&h0);
    u.y = *reinterpret_cast<unsigned*>(&h1);
    __half* dst = (row < M_TGT) ? (g_tgt_h + (size_t)row * KD)
                                : (g_pred_h + (size_t)(row - M_TGT) * KD);
    *(uint2*)(dst + lane * 4) = u;
    if (lane == 0) {
        if (row < M_TGT) g_b2[row] = s;
        else             g_a2[row - M_TGT] = s;
    }
}

// ---------------- main: HMMA GEMM + fused per-row top-5 ----------------
extern __shared__ char smem[];

__global__ __launch_bounds__(256, 2) void mma_main() {
    const int tid  = threadIdx.x;
    const int wid  = tid >> 5;      // warp owns pred rows 16*wid .. 16*wid+15
    const int lane = tid & 31;
    const uint32_t sbase = smem_u32(smem);

    const int row0 = blockIdx.x * MT;
    const int tb0  = blockIdx.y * CHUNK;

    // ---- prologue: A tile (128x128h) + B tile 0 (64x128h) + b2 ----
    {
        const char* gA = (const char*)g_pred_h + (size_t)row0 * 256;
        const char* gB = (const char*)g_tgt_h + (size_t)tb0 * 256;
        #pragma unroll
        for (int i = 0; i < 8; i++) {           // 2048 16B chunks for A
            int cix = tid + i * 256;
            int r = cix >> 4, c = cix & 15;
            cp16(sbase + SA + r * ROWB + c * 16, gA + (size_t)r * 256 + c * 16);
        }
        #pragma unroll
        for (int i = 0; i < 4; i++) {           // 1024 16B chunks for B
            int cix = tid + i * 256;
            int r = cix >> 4, c = cix & 15;
            cp16(sbase + SB0 + r * ROWB + c * 16, gB + (size_t)r * 256 + c * 16);
        }
        if (tid < NT) cp4(sbase + B2_0 + tid * 4, g_b2 + tb0 + tid);
        CP_COMMIT();
        CP_WAIT0();
    }
    __syncthreads();

    // ldmatrix per-lane byte offsets
    const uint32_t rowA_off =
        (uint32_t)(wid * 16 + ((lane >> 3) & 1) * 8 + (lane & 7)) * ROWB +
        (uint32_t)(lane >> 4) * 16;
    const uint32_t rowB_off =
        (uint32_t)(((lane >> 4) & 1) * 8 + (lane & 7)) * ROWB +
        (uint32_t)((lane >> 3) & 1) * 16;

    float t5[2][TOPK];
    #pragma unroll
    for (int r = 0; r < 2; r++)
        #pragma unroll
        for (int s = 0; s < TOPK; s++) t5[r][s] = FLT_MAX;

    for (int tile = 0; tile < TILES; tile++) {
        const int p = tile & 1;
        const uint32_t sb_cur = sbase + (p ? SB1 : SB0);
        const uint32_t b2_cur = sbase + (p ? B2_1 : B2_0);

        // prefetch next B tile
        if (tile + 1 < TILES) {
            const uint32_t sb_nxt = sbase + (p ? SB0 : SB1);
            const uint32_t b2_nxt = sbase + (p ? B2_0 : B2_1);
            const int tb = tb0 + (tile + 1) * NT;
            const char* gB = (const char*)g_tgt_h + (size_t)tb * 256;
            #pragma unroll
            for (int i = 0; i < 4; i++) {
                int cix = tid + i * 256;
                int r = cix >> 4, c = cix & 15;
                cp16(sb_nxt + r * ROWB + c * 16, gB + (size_t)r * 256 + c * 16);
            }
            if (tid < NT) cp4(b2_nxt + tid * 4, g_b2 + tb + tid);
            CP_COMMIT();
        }

        // ---- C(16x64) = A_warp(16x128) . B^T ----
        float acc[8][4];
        #pragma unroll
        for (int nf = 0; nf < 8; nf++)
            #pragma unroll
            for (int i = 0; i < 4; i++) acc[nf][i] = 0.0f;

        #pragma unroll
        for (int ks = 0; ks < 8; ks++) {
            uint32_t a0, a1, a2, a3;
            ldsm4(sbase + SA + rowA_off + ks * 32, a0, a1, a2, a3);
            #pragma unroll
            for (int j = 0; j < 4; j++) {
                uint32_t b0, b1, b2, b3;
                ldsm4(sb_cur + rowB_off + j * (16 * ROWB) + ks * 32, b0, b1, b2, b3);
                mma16816(acc[2 * j + 0], a0, a1, a2, a3, b0, b1);
                mma16816(acc[2 * j + 1], a0, a1, a2, a3, b2, b3);
            }
        }

        // ---- epilogue: keys + top-5 insert (2 rows/thread) ----
        #pragma unroll
        for (int nf = 0; nf < 8; nf++) {
            float bb0 = *(const float*)(smem + (b2_cur - sbase) +
                                        (nf * 8 + 2 * (lane & 3) + 0) * 4);
            float bb1 = *(const float*)(smem + (b2_cur - sbase) +
                                        (nf * 8 + 2 * (lane & 3) + 1) * 4);
            #pragma unroll
            for (int i = 0; i < 4; i++) {
                const int ri = i >> 1;
                float key = fmaf(-2.0f, acc[nf][i], (i & 1) ? bb1 : bb0);
                if (key < t5[ri][4]) {
                    t5[ri][4] = key;
                    CE(t5[ri][3], t5[ri][4]);
                    CE(t5[ri][2], t5[ri][3]);
                    CE(t5[ri][1], t5[ri][2]);
                    CE(t5[ri][0], t5[ri][1]);
                }
            }
        }

        CP_WAIT0();
        __syncthreads();
    }

    // ---- quad merge: lanes 4g..4g+3 share rows g and g+8 ----
    #pragma unroll
    for (int r = 0; r < 2; r++) {
        #pragma unroll
        for (int off = 1; off <= 2; off <<= 1) {
            float b[TOPK], m[TOPK];
            #pragma unroll
            for (int s = 0; s < TOPK; s++)
                b[s] = __shfl_xor_sync(0xffffffffu, t5[r][s], off);
            #pragma unroll
            for (int s = 0; s < TOPK; s++)
                m[s] = fminf(t5[r][s], b[TOPK - 1 - s]);
            CE(m[0], m[1]); CE(m[1], m[2]); CE(m[2], m[3]); CE(m[3], m[4]);
            CE(m[0], m[1]); CE(m[1], m[2]); CE(m[2], m[3]);
            CE(m[0], m[1]); CE(m[1], m[2]);
            CE(m[0], m[1]);
            #pragma unroll
            for (int s = 0; s < TOPK; s++) t5[r][s] = m[s];
        }
    }

    if ((lane & 3) == 0) {
        #pragma unroll
        for (int r = 0; r < 2; r++) {
            int row = row0 + wid * 16 + (lane >> 2) + 8 * r;
            size_t base = ((size_t)blockIdx.y * N_PRED + row) * TOPK;
            #pragma unroll
            for (int s = 0; s < TOPK; s++)
                g_cand[base + s] = t5[r][s];
        }
    }
}

// ---------------- merge chunks -> hinge sums -> (last block) final ----------------
__global__ void merge_kernel(float* __restrict__ out) {
    __shared__ float ws[8];
    __shared__ int is_last;
    int r = blockIdx.x * 256 + threadIdx.x;
    float t5[TOPK];
    #pragma unroll
    for (int s = 0; s < TOPK; s++) t5[s] = FLT_MAX;
    #pragma unroll
    for (int c = 0; c < CHUNKS; c++)
        #pragma unroll
        for (int j = 0; j < TOPK; j++) {
            float key = g_cand[((size_t)c * N_PRED + r) * TOPK + j];
            if (key < t5[4]) {
                t5[4] = key;
                CE(t5[3], t5[4]); CE(t5[2], t5[3]); CE(t5[1], t5[2]); CE(t5[0], t5[1]);
            }
        }
    float a2 = g_a2[r];
    float sum = 0.0f;
    #pragma unroll
    for (int s = 0; s < TOPK; s++) {
        float d2 = fmaxf(a2 + t5[s], 0.0f);
        sum += fmaxf(sqrtf(d2) - 1.0f, 0.0f);
    }
    #pragma unroll
    for (int off = 16; off; off >>= 1)
        sum += __shfl_xor_sync(0xffffffffu, sum, off);
    if ((threadIdx.x & 31) == 0) ws[threadIdx.x >> 5] = sum;
    __syncthreads();
    if (threadIdx.x == 0) {
        float t = 0.0f;
        #pragma unroll
        for (int w = 0; w < 8; w++) t += ws[w];
        g_partials[blockIdx.x] = t;
        __threadfence();
        int v = atomicAdd(&g_ticket, 1);
        is_last = (v == 31) ? 1 : 0;
    }
    __syncthreads();
    if (is_last && threadIdx.x == 0) {
        __threadfence();
        float t = 0.0f;
        #pragma unroll
        for (int b = 0; b < 32; b++) t += g_partials[b];   // fixed order: deterministic
        out[0] = t * (1.0f / ((float)N_PRED * (float)TOPK));
    }
}

extern "C" void kernel_launch(void* const* d_in, const int* in_sizes, int n_in,
                              void* d_out, int out_size) {
    const float* pred = (const float*)d_in[0];
    const float* tgt  = (const float*)d_in[1];

    prep_kernel<<<(N_PRED + M_TGT + 7) / 8, 256>>>(pred, tgt);

    cudaFuncSetAttribute(mma_main, cudaFuncAttributeMaxDynamicSharedMemorySize,
                         SMEM_TOTAL);
    dim3 grid(N_PRED / MT, CHUNKS);
    mma_main<<<grid, 256, SMEM_TOTAL>>>();

    merge_kernel<<<N_PRED / 256, 256>>>((float*)d_out);
}

// round 5
// speedup vs baseline: 6.9098x; 1.0393x over previous
#include <cuda_runtime.h>
#include <cuda_fp16.h>
#include <math.h>
#include <float.h>
#include <stdint.h>

#define N_PRED 8192
#define M_TGT  16384
#define KD     128
#define MT     128         // CTA tile M (pred rows)
#define NT     128         // CTA tile N (target rows)
#define CHUNKS 4
#define CHUNK  (M_TGT / CHUNKS)   // 4096
#define TILES  (CHUNK / NT)       // 32
#define TOPK   5
#define ROWB   272         // bytes per padded smem row (136 halves)

// ---------------- static device scratch ----------------
__device__ __half g_pred_h[N_PRED * KD];
__device__ __half g_tgt_h[M_TGT * KD];
__device__ float  g_a2[N_PRED];
__device__ float  g_b2[M_TGT];
__device__ float  g_cand[CHUNKS * N_PRED * 2 * TOPK];  // [chunk][row][warpN][5]
__device__ float  g_partials[32];
__device__ int    g_ticket;

// ---------------- smem layout (bytes), per CTA 105472 ----------------
#define SA    0
#define SB0   34816
#define SB1   69632
#define B2_0  104448
#define B2_1  104960
#define SMEM_TOTAL 105472

__device__ __forceinline__ uint32_t smem_u32(const void* p) {
    uint32_t a;
    asm("{ .reg .u64 t; cvta.to.shared.u64 t, %1; cvt.u32.u64 %0, t; }"
        : "=r"(a) : "l"(p));
    return a;
}
__device__ __forceinline__ void cp16(uint32_t dst, const void* src) {
    asm volatile("cp.async.cg.shared.global [%0], [%1], 16;"
                 :: "r"(dst), "l"(src) : "memory");
}
__device__ __forceinline__ void cp4(uint32_t dst, const void* src) {
    asm volatile("cp.async.ca.shared.global [%0], [%1], 4;"
                 :: "r"(dst), "l"(src) : "memory");
}
#define CP_COMMIT() asm volatile("cp.async.commit_group;" ::: "memory")
#define CP_WAIT0()  asm volatile("cp.async.wait_group 0;" ::: "memory")

__device__ __forceinline__ void ldsm4(uint32_t a, uint32_t& r0, uint32_t& r1,
                                      uint32_t& r2, uint32_t& r3) {
    asm volatile("ldmatrix.sync.aligned.m8n8.x4.shared.b16 {%0,%1,%2,%3}, [%4];"
                 : "=r"(r0), "=r"(r1), "=r"(r2), "=r"(r3) : "r"(a));
}
// fp16-accumulate HMMA: D(f16x2 pair) = A*B + D
__device__ __forceinline__ void mma16816_f16(uint32_t& d0, uint32_t& d1,
                                             uint32_t a0, uint32_t a1,
                                             uint32_t a2, uint32_t a3,
                                             uint32_t b0, uint32_t b1) {
    asm volatile("mma.sync.aligned.m16n8k16.row.col.f16.f16.f16.f16 "
                 "{%0,%1}, {%2,%3,%4,%5}, {%6,%7}, {%0,%1};"
                 : "+r"(d0), "+r"(d1)
                 : "r"(a0), "r"(a1), "r"(a2), "r"(a3), "r"(b0), "r"(b1));
}

#define CE(x, y) { float _lo = fminf(x, y); float _hi = fmaxf(x, y); x = _lo; y = _hi; }

// ---------------- prep: fp32 -> fp16 convert + squared norms ----------------
__global__ void prep_kernel(const float* __restrict__ pred,
                            const float* __restrict__ tgt) {
    if (blockIdx.x == 0 && threadIdx.x == 0) g_ticket = 0;
    int row  = blockIdx.x * 8 + (threadIdx.x >> 5);
    int lane = threadIdx.x & 31;
    if (row >= N_PRED + M_TGT) return;
    const float* src = (row < M_TGT) ? (tgt + (size_t)row * KD)
                                     : (pred + (size_t)(row - M_TGT) * KD);
    float4 v = ((const float4*)src)[lane];
    float s = v.x * v.x + v.y * v.y + v.z * v.z + v.w * v.w;
    #pragma unroll
    for (int off = 16; off; off >>= 1)
        s += __shfl_xor_sync(0xffffffffu, s, off);
    __half2 h0 = __floats2half2_rn(v.x, v.y);
    __half2 h1 = __floats2half2_rn(v.z, v.w);
    uint2 u;
    u.x = *reinterpret_cast<unsigned*>(&h0);
    u.y = *reinterpret_cast<unsigned*>(&h1);
    __half* dst = (row < M_TGT) ? (g_tgt_h + (size_t)row * KD)
                                : (g_pred_h + (size_t)(row - M_TGT) * KD);
    *(uint2*)(dst + lane * 4) = u;
    if (lane == 0) {
        if (row < M_TGT) g_b2[row] = s;
        else             g_a2[row - M_TGT] = s;
    }
}

// ---------------- main: HMMA(f16 acc) GEMM + fused per-row top-5 ----------------
extern __shared__ char smem[];

__global__ __launch_bounds__(256, 2) void mma_main() {
    const int tid   = threadIdx.x;
    const int wid   = tid >> 5;
    const int lane  = tid & 31;
    const int warpM = wid >> 1;     // 0..3  (32 pred rows each)
    const int warpN = wid & 1;      // 0..1  (64 target cols each)
    const uint32_t sbase = smem_u32(smem);

    const int row0 = blockIdx.x * MT;
    const int tb0  = blockIdx.y * CHUNK;

    // ---- prologue: A tile (128x128h) + B tile 0 (128x128h) + b2 ----
    {
        const char* gA = (const char*)g_pred_h + (size_t)row0 * 256;
        const char* gB = (const char*)g_tgt_h + (size_t)tb0 * 256;
        #pragma unroll
        for (int i = 0; i < 8; i++) {
            int cix = tid + i * 256;
            int r = cix >> 4, c = cix & 15;
            cp16(sbase + SA + r * ROWB + c * 16, gA + (size_t)r * 256 + c * 16);
            cp16(sbase + SB0 + r * ROWB + c * 16, gB + (size_t)r * 256 + c * 16);
        }
        if (tid < NT) cp4(sbase + B2_0 + tid * 4, g_b2 + tb0 + tid);
        CP_COMMIT();
        CP_WAIT0();
    }
    __syncthreads();

    // per-lane ldmatrix byte offsets
    const uint32_t rowA_off =
        (uint32_t)(warpM * 32 + ((lane >> 3) & 1) * 8 + (lane & 7)) * ROWB +
        (uint32_t)(lane >> 4) * 16;
    const uint32_t rowB_off =
        (uint32_t)(warpN * 64 + ((lane >> 4) & 1) * 8 + (lane & 7)) * ROWB +
        (uint32_t)((lane >> 3) & 1) * 16;

    float t5[4][TOPK];
    #pragma unroll
    for (int r = 0; r < 4; r++)
        #pragma unroll
        for (int s = 0; s < TOPK; s++) t5[r][s] = FLT_MAX;

    for (int tile = 0; tile < TILES; tile++) {
        const int p = tile & 1;
        const uint32_t sb_cur = sbase + (p ? SB1 : SB0);
        const uint32_t b2_cur = sbase + (p ? B2_1 : B2_0);

        // prefetch next B tile
        if (tile + 1 < TILES) {
            const uint32_t sb_nxt = sbase + (p ? SB0 : SB1);
            const uint32_t b2_nxt = sbase + (p ? B2_0 : B2_1);
            const int tb = tb0 + (tile + 1) * NT;
            const char* gB = (const char*)g_tgt_h + (size_t)tb * 256;
            #pragma unroll
            for (int i = 0; i < 8; i++) {
                int cix = tid + i * 256;
                int r = cix >> 4, c = cix & 15;
                cp16(sb_nxt + r * ROWB + c * 16, gB + (size_t)r * 256 + c * 16);
            }
            if (tid < NT) cp4(b2_nxt + tid * 4, g_b2 + tb + tid);
            CP_COMMIT();
        }

        // ---- C(32x64, fp16 acc) = A_warp(32x128) . B_warp^T ----
        uint32_t acc[2][8][2];     // [mf][nf][pair]
        #pragma unroll
        for (int mf = 0; mf < 2; mf++)
            #pragma unroll
            for (int nf = 0; nf < 8; nf++) {
                acc[mf][nf][0] = 0u;
                acc[mf][nf][1] = 0u;
            }

        #pragma unroll
        for (int ks = 0; ks < 8; ks++) {
            uint32_t a[2][4];
            #pragma unroll
            for (int mf = 0; mf < 2; mf++)
                ldsm4(sbase + SA + rowA_off + mf * (16 * ROWB) + ks * 32,
                      a[mf][0], a[mf][1], a[mf][2], a[mf][3]);
            #pragma unroll
            for (int j = 0; j < 4; j++) {
                uint32_t b0, b1, b2, b3;
                ldsm4(sb_cur + rowB_off + j * (16 * ROWB) + ks * 32, b0, b1, b2, b3);
                #pragma unroll
                for (int mf = 0; mf < 2; mf++) {
                    mma16816_f16(acc[mf][2 * j + 0][0], acc[mf][2 * j + 0][1],
                                 a[mf][0], a[mf][1], a[mf][2], a[mf][3], b0, b1);
                    mma16816_f16(acc[mf][2 * j + 1][0], acc[mf][2 * j + 1][1],
                                 a[mf][0], a[mf][1], a[mf][2], a[mf][3], b2, b3);
                }
            }
        }

        // ---- epilogue: fp32 keys + top-5 insert (4 rows/thread) ----
        #pragma unroll
        for (int nf = 0; nf < 8; nf++) {
            float bb0 = *(const float*)(smem + (b2_cur - sbase) +
                         (warpN * 64 + nf * 8 + 2 * (lane & 3) + 0) * 4);
            float bb1 = *(const float*)(smem + (b2_cur - sbase) +
                         (warpN * 64 + nf * 8 + 2 * (lane & 3) + 1) * 4);
            #pragma unroll
            for (int mf = 0; mf < 2; mf++)
                #pragma unroll
                for (int h = 0; h < 2; h++) {
                    const int ri = mf * 2 + h;
                    float2 f = __half22float2(
                        *reinterpret_cast<__half2*>(&acc[mf][nf][h]));
                    float k0 = fmaf(-2.0f, f.x, bb0);
                    float k1 = fmaf(-2.0f, f.y, bb1);
                    if (k0 < t5[ri][4]) {
                        t5[ri][4] = k0;
                        CE(t5[ri][3], t5[ri][4]); CE(t5[ri][2], t5[ri][3]);
                        CE(t5[ri][1], t5[ri][2]); CE(t5[ri][0], t5[ri][1]);
                    }
                    if (k1 < t5[ri][4]) {
                        t5[ri][4] = k1;
                        CE(t5[ri][3], t5[ri][4]); CE(t5[ri][2], t5[ri][3]);
                        CE(t5[ri][1], t5[ri][2]); CE(t5[ri][0], t5[ri][1]);
                    }
                }
        }

        CP_WAIT0();
        __syncthreads();
    }

    // ---- quad merge: lanes 4g..4g+3 share the same rows ----
    #pragma unroll
    for (int r = 0; r < 4; r++) {
        #pragma unroll
        for (int off = 1; off <= 2; off <<= 1) {
            float b[TOPK], m[TOPK];
            #pragma unroll
            for (int s = 0; s < TOPK; s++)
                b[s] = __shfl_xor_sync(0xffffffffu, t5[r][s], off);
            #pragma unroll
            for (int s = 0; s < TOPK; s++)
                m[s] = fminf(t5[r][s], b[TOPK - 1 - s]);
            CE(m[0], m[1]); CE(m[1], m[2]); CE(m[2], m[3]); CE(m[3], m[4]);
            CE(m[0], m[1]); CE(m[1], m[2]); CE(m[2], m[3]);
            CE(m[0], m[1]); CE(m[1], m[2]);
            CE(m[0], m[1]);
            #pragma unroll
            for (int s = 0; s < TOPK; s++) t5[r][s] = m[s];
        }
    }

    if ((lane & 3) == 0) {
        #pragma unroll
        for (int mf = 0; mf < 2; mf++)
            #pragma unroll
            for (int h = 0; h < 2; h++) {
                int row = row0 + warpM * 32 + mf * 16 + (lane >> 2) + 8 * h;
                size_t base = ((size_t)blockIdx.y * N_PRED + row) * (2 * TOPK) +
                              warpN * TOPK;
                #pragma unroll
                for (int s = 0; s < TOPK; s++)
                    g_cand[base + s] = t5[mf * 2 + h][s];
            }
    }
}

// ---------------- merge chunks -> hinge sums -> (last block) final ----------------
__global__ void merge_kernel(float* __restrict__ out) {
    __shared__ float ws[8];
    __shared__ int is_last;
    int r = blockIdx.x * 256 + threadIdx.x;
    float t5[TOPK];
    #pragma unroll
    for (int s = 0; s < TOPK; s++) t5[s] = FLT_MAX;
    #pragma unroll
    for (int c = 0; c < CHUNKS; c++)
        #pragma unroll
        for (int j = 0; j < 2 * TOPK; j++) {
            float key = g_cand[((size_t)c * N_PRED + r) * (2 * TOPK) + j];
            if (key < t5[4]) {
                t5[4] = key;
                CE(t5[3], t5[4]); CE(t5[2], t5[3]); CE(t5[1], t5[2]); CE(t5[0], t5[1]);
            }
        }
    float a2 = g_a2[r];
    float sum = 0.0f;
    #pragma unroll
    for (int s = 0; s < TOPK; s++) {
        float d2 = fmaxf(a2 + t5[s], 0.0f);
        sum += fmaxf(sqrtf(d2) - 1.0f, 0.0f);
    }
    #pragma unroll
    for (int off = 16; off; off >>= 1)
        sum += __shfl_xor_sync(0xffffffffu, sum, off);
    if ((threadIdx.x & 31) == 0) ws[threadIdx.x >> 5] = sum;
    __syncthreads();
    if (threadIdx.x == 0) {
        float t = 0.0f;
        #pragma unroll
        for (int w = 0; w < 8; w++) t += ws[w];
        g_partials[blockIdx.x] = t;
        __threadfence();
        int v = atomicAdd(&g_ticket, 1);
        is_last = (v == 31) ? 1 : 0;
    }
    __syncthreads();
    if (is_last && threadIdx.x == 0) {
        __threadfence();
        float t = 0.0f;
        #pragma unroll
        for (int b = 0; b < 32; b++) t += g_partials[b];   // fixed order
        out[0] = t * (1.0f / ((float)N_PRED * (float)TOPK));
    }
}

extern "C" void kernel_launch(void* const* d_in, const int* in_sizes, int n_in,
                              void* d_out, int out_size) {
    const float* pred = (const float*)d_in[0];
    const float* tgt  = (const float*)d_in[1];

    prep_kernel<<<(N_PRED + M_TGT + 7) / 8, 256>>>(pred, tgt);

    cudaFuncSetAttribute(mma_main, cudaFuncAttributeMaxDynamicSharedMemorySize,
                         SMEM_TOTAL);
    dim3 grid(N_PRED / MT, CHUNKS);
    mma_main<<<grid, 256, SMEM_TOTAL>>>();

    merge_kernel<<<N_PRED / 256, 256>>>((float*)d_out);
}